// round 2
// baseline (speedup 1.0000x reference)
#include <cuda_runtime.h>
#include <math.h>

#define B_ 8
#define C_ 512
#define L_ 2048
#define D_ 64

// Scratch (allocation-free rule: device globals)
__device__ float g_q[B_*D_*L_];     // (b, d, l)
__device__ float g_k[B_*D_*L_];     // (b, d, l)
__device__ float g_v[(size_t)B_*C_*L_];  // (b, c, l)

// ---------------------------------------------------------------------------
// Kernel 1: fused QKV projection.  Rows 0..63 -> q, 64..127 -> k, 128..639 -> v
// Computes W_all (640x512) @ x_b (512x2048) + bias, per batch.
// 64x64 tile, 256 threads, 4x4 micro-tile, BK=16.
// ---------------------------------------------------------------------------
__global__ __launch_bounds__(256) void qkv_proj_kernel(
    const float* __restrict__ x,
    const float* __restrict__ Wq, const float* __restrict__ bq,
    const float* __restrict__ Wk, const float* __restrict__ bk,
    const float* __restrict__ Wv, const float* __restrict__ bv)
{
    const int b  = blockIdx.z;
    const int r0 = blockIdx.y * 64;   // output row tile (640 rows total)
    const int l0 = blockIdx.x * 64;   // l tile
    const int tid = threadIdx.x;
    const int tx = tid & 15, ty = tid >> 4;

    __shared__ __align__(16) float As[16][68];
    __shared__ __align__(16) float Bs[16][68];

    float acc[4][4] = {};
    const float* xb = x + (size_t)b * C_ * L_;

    for (int kc = 0; kc < C_; kc += 16) {
        // A tile: 64 rows x 16 k (weights)
        {
            const int k = tid & 15;
            const int m = tid >> 4;       // 0..15
            #pragma unroll
            for (int p = 0; p < 4; p++) {
                const int rr = r0 + m + p*16;
                const int cc = kc + k;
                float w;
                if (rr < 64)       w = Wq[rr*C_ + cc];
                else if (rr < 128) w = Wk[(rr-64)*C_ + cc];
                else               w = Wv[(rr-128)*C_ + cc];
                As[k][m + p*16] = w;
            }
        }
        // B tile: 16 k x 64 l (x), coalesced along l
        {
            const int l = tid & 63;
            const int k = tid >> 6;       // 0..3
            #pragma unroll
            for (int p = 0; p < 4; p++)
                Bs[k + p*4][l] = xb[(size_t)(kc + k + p*4) * L_ + l0 + l];
        }
        __syncthreads();
        #pragma unroll
        for (int kk = 0; kk < 16; kk++) {
            const float4 a4 = *reinterpret_cast<const float4*>(&As[kk][ty*4]);
            const float4 b4 = *reinterpret_cast<const float4*>(&Bs[kk][tx*4]);
            const float a[4] = {a4.x, a4.y, a4.z, a4.w};
            const float bb[4] = {b4.x, b4.y, b4.z, b4.w};
            #pragma unroll
            for (int i = 0; i < 4; i++)
                #pragma unroll
                for (int j = 0; j < 4; j++)
                    acc[i][j] += a[i] * bb[j];
        }
        __syncthreads();
    }
    // Epilogue: add bias, scatter to q/k/v scratch
    #pragma unroll
    for (int i = 0; i < 4; i++) {
        const int r = r0 + ty*4 + i;
        float bias;
        float* dst;
        if (r < 64)       { bias = bq[r];      dst = g_q + ((size_t)b*D_ + r)      * L_; }
        else if (r < 128) { bias = bk[r-64];   dst = g_k + ((size_t)b*D_ + (r-64)) * L_; }
        else              { bias = bv[r-128];  dst = g_v + ((size_t)b*C_ + (r-128))* L_; }
        #pragma unroll
        for (int j = 0; j < 4; j++)
            dst[l0 + tx*4 + j] = acc[i][j] + bias;
    }
}

// ---------------------------------------------------------------------------
// Kernel 2: energy[b,l,m] = sum_d q[b,d,l] * k[b,d,m], lower-triangular tiles only.
// Writes raw energy into the attention output region (softmax runs in-place).
// ---------------------------------------------------------------------------
__global__ __launch_bounds__(256) void energy_kernel(float* __restrict__ att)
{
    const int b  = blockIdx.z;
    const int lt = blockIdx.y;
    const int mt = blockIdx.x;
    if (mt > lt) return;              // strictly above diagonal: fully masked
    const int l0 = lt * 64, m0 = mt * 64;
    const int tid = threadIdx.x;
    const int tx = tid & 15, ty = tid >> 4;

    __shared__ __align__(16) float Qs[64][68];
    __shared__ __align__(16) float Ks[64][68];

    const float* qb = g_q + (size_t)b * D_ * L_;
    const float* kb = g_k + (size_t)b * D_ * L_;
    {
        const int l  = tid & 63;
        const int d4 = tid >> 6;      // 0..3
        #pragma unroll
        for (int p = 0; p < 16; p++) {
            const int d = d4 + p*4;
            Qs[d][l] = qb[(size_t)d * L_ + l0 + l];
            Ks[d][l] = kb[(size_t)d * L_ + m0 + l];
        }
    }
    __syncthreads();

    float acc[4][4] = {};
    #pragma unroll 16
    for (int kk = 0; kk < 64; kk++) {
        const float4 a4 = *reinterpret_cast<const float4*>(&Qs[kk][ty*4]);
        const float4 b4 = *reinterpret_cast<const float4*>(&Ks[kk][tx*4]);
        const float a[4]  = {a4.x, a4.y, a4.z, a4.w};
        const float bb[4] = {b4.x, b4.y, b4.z, b4.w};
        #pragma unroll
        for (int i = 0; i < 4; i++)
            #pragma unroll
            for (int j = 0; j < 4; j++)
                acc[i][j] += a[i] * bb[j];
    }

    float* ab = att + (size_t)b * L_ * L_;
    #pragma unroll
    for (int i = 0; i < 4; i++)
        #pragma unroll
        for (int j = 0; j < 4; j++)
            ab[(size_t)(l0 + ty*4 + i) * L_ + m0 + tx*4 + j] = acc[i][j];
}

// ---------------------------------------------------------------------------
// Kernel 3: per-row causal softmax (in-place over attention region).
// Row l: valid m in [0, l]; data_mask -> -inf; m > l -> write exact 0.
// ---------------------------------------------------------------------------
__device__ __forceinline__ float block_reduce(float v, float* red, bool is_max)
{
    #pragma unroll
    for (int o = 16; o > 0; o >>= 1) {
        const float t = __shfl_xor_sync(0xffffffffu, v, o);
        v = is_max ? fmaxf(v, t) : (v + t);
    }
    const int w = threadIdx.x >> 5;
    if ((threadIdx.x & 31) == 0) red[w] = v;
    __syncthreads();
    if (threadIdx.x < 32) {
        float t = (threadIdx.x < 8) ? red[threadIdx.x] : (is_max ? -INFINITY : 0.0f);
        #pragma unroll
        for (int o = 4; o > 0; o >>= 1) {
            const float u = __shfl_xor_sync(0xffffffffu, t, o);
            t = is_max ? fmaxf(t, u) : (t + u);
        }
        if (threadIdx.x == 0) red[0] = t;
    }
    __syncthreads();
    const float r = red[0];
    __syncthreads();   // protect red[] reuse
    return r;
}

__global__ __launch_bounds__(256) void softmax_kernel(
    float* __restrict__ att, const unsigned char* __restrict__ dmask)
{
    const int l = blockIdx.x;
    const int b = blockIdx.y;
    const int tid = threadIdx.x;

    __shared__ float row[L_];
    __shared__ float red[32];

    float* arow = att + ((size_t)b * L_ + l) * L_;
    const unsigned char* mrow = dmask + ((size_t)b * L_ + l) * L_;
    const int n = l + 1;

    float lmax = -INFINITY;
    for (int m = tid; m < n; m += 256) {
        float e = arow[m];
        if (mrow[m]) e = -INFINITY;
        row[m] = e;
        lmax = fmaxf(lmax, e);
    }
    const float rmax = block_reduce(lmax, red, true);

    float lsum = 0.0f;
    for (int m = tid; m < n; m += 256) {
        const float p = __expf(row[m] - rmax);
        row[m] = p;
        lsum += p;
    }
    const float rsum = block_reduce(lsum, red, false);
    const float inv = 1.0f / rsum;

    for (int m = tid; m < n; m += 256) arow[m] = row[m] * inv;
    for (int m = n + tid; m < L_; m += 256) arow[m] = 0.0f;
}

// ---------------------------------------------------------------------------
// Kernel 4: out[b,c,m] = sum_l v[b,c,l] * att[b,m,l].
// Causal: att[m,l] = 0 for l > m, so K-loop truncated to l < m0 + 64.
// ---------------------------------------------------------------------------
__global__ __launch_bounds__(256) void out_gemm_kernel(
    const float* __restrict__ att, float* __restrict__ out)
{
    const int b  = blockIdx.z;
    const int c0 = blockIdx.y * 64;
    const int m0 = blockIdx.x * 64;
    const int tid = threadIdx.x;
    const int tx = tid & 15, ty = tid >> 4;

    __shared__ __align__(16) float Vs[16][68];
    __shared__ __align__(16) float Bs[16][68];

    const float* vb = g_v + (size_t)b * C_ * L_;
    const float* ab = att + (size_t)b * L_ * L_;

    float acc[4][4] = {};
    const int kend = m0 + 64;         // att rows in this tile see only l <= m0+63

    for (int lc = 0; lc < kend; lc += 16) {
        {
            const int k = tid & 15;
            const int m = tid >> 4;   // 0..15
            #pragma unroll
            for (int p = 0; p < 4; p++) {
                Vs[k][m + p*16] = vb[(size_t)(c0 + m + p*16) * L_ + lc + k];
                Bs[k][m + p*16] = ab[(size_t)(m0 + m + p*16) * L_ + lc + k];
            }
        }
        __syncthreads();
        #pragma unroll
        for (int kk = 0; kk < 16; kk++) {
            const float4 a4 = *reinterpret_cast<const float4*>(&Vs[kk][ty*4]);
            const float4 b4 = *reinterpret_cast<const float4*>(&Bs[kk][tx*4]);
            const float a[4]  = {a4.x, a4.y, a4.z, a4.w};
            const float bb[4] = {b4.x, b4.y, b4.z, b4.w};
            #pragma unroll
            for (int i = 0; i < 4; i++)
                #pragma unroll
                for (int j = 0; j < 4; j++)
                    acc[i][j] += a[i] * bb[j];
        }
        __syncthreads();
    }

    float* ob = out + (size_t)b * C_ * L_;
    #pragma unroll
    for (int i = 0; i < 4; i++)
        #pragma unroll
        for (int j = 0; j < 4; j++)
            ob[(size_t)(c0 + ty*4 + i) * L_ + m0 + tx*4 + j] = acc[i][j];
}

// ---------------------------------------------------------------------------
extern "C" void kernel_launch(void* const* d_in, const int* in_sizes, int n_in,
                              void* d_out, int out_size)
{
    (void)in_sizes; (void)n_in; (void)out_size;
    const float* x          = (const float*)d_in[0];
    const unsigned char* dm = (const unsigned char*)d_in[1];
    const float* Wq = (const float*)d_in[2];
    const float* bq = (const float*)d_in[3];
    const float* Wk = (const float*)d_in[4];
    const float* bk = (const float*)d_in[5];
    const float* Wv = (const float*)d_in[6];
    const float* bv = (const float*)d_in[7];

    float* out = (float*)d_out;                      // (B, C, L)
    float* att = out + (size_t)B_ * C_ * L_;         // (B, L, L)

    qkv_proj_kernel<<<dim3(L_/64, 640/64, B_), 256>>>(x, Wq, bq, Wk, bk, Wv, bv);
    energy_kernel  <<<dim3(L_/64, L_/64, B_), 256>>>(att);
    softmax_kernel <<<dim3(L_, B_), 256>>>(att, dm);
    out_gemm_kernel<<<dim3(L_/64, C_/64, B_), 256>>>(att, out);
}

// round 3
// speedup vs baseline: 1.1401x; 1.1401x over previous
#include <cuda_runtime.h>
#include <math.h>

#define B_ 8
#define C_ 512
#define L_ 2048
#define D_ 64

// Scratch (allocation-free rule: device globals)
__device__ float g_q[B_*D_*L_];          // (b, d, l)
__device__ float g_k[B_*D_*L_];          // (b, d, l)
__device__ float g_v[(size_t)B_*C_*L_];  // (b, c, l)

// ===========================================================================
// Kernel 1: fused QKV projection.  W_all(640x512) @ x_b(512x2048) + bias.
// 128x128 tile, 256 threads, 8x8 micro-tile (2x2 quadrants of 4x4), BK=16.
// Rows 0..63 -> q, 64..127 -> k, 128..639 -> v.
// ===========================================================================
__device__ __forceinline__ const float* w_row_ptr(
    int r, const float* Wq, const float* Wk, const float* Wv)
{
    return (r < 64)  ? Wq + (size_t)r * C_
         : (r < 128) ? Wk + (size_t)(r - 64) * C_
                     : Wv + (size_t)(r - 128) * C_;
}

__global__ __launch_bounds__(256) void qkv_proj_kernel(
    const float* __restrict__ x,
    const float* __restrict__ Wq, const float* __restrict__ bq,
    const float* __restrict__ Wk, const float* __restrict__ bk,
    const float* __restrict__ Wv, const float* __restrict__ bv)
{
    const int b  = blockIdx.z;
    const int r0 = blockIdx.y * 128;   // output row tile (640 rows total)
    const int l0 = blockIdx.x * 128;   // l tile
    const int tid = threadIdx.x;
    const int tx = tid & 15, ty = tid >> 4;

    __shared__ __align__(16) float As[16][132];   // [k][row]
    __shared__ __align__(16) float Bs[16][132];   // [k][l]

    const float* xb = x + (size_t)b * C_ * L_;

    // A-tile assignment: thread loads float4 at (rowA, kqA*4) and (rowA+64, kqA*4)
    const int rowA = tid >> 2;         // 0..63
    const int kqA  = tid & 3;          // float4 slot within BK=16
    const float* aptr0 = w_row_ptr(r0 + rowA,      Wq, Wk, Wv) + kqA * 4;
    const float* aptr1 = w_row_ptr(r0 + rowA + 64, Wq, Wk, Wv) + kqA * 4;

    // B-tile assignment: Bs[k][l] direct (k slow in x): f = tid + it*256
    const int kB  = tid >> 5;          // 0..7  (and +8)
    const int l4B = tid & 31;          // float4 col

    float acc[2][2][4][4] = {};

    for (int kc = 0; kc < C_; kc += 16) {
        {
            float4 a0 = *(const float4*)(aptr0 + kc);
            float4 a1 = *(const float4*)(aptr1 + kc);
            As[kqA*4+0][rowA]    = a0.x; As[kqA*4+1][rowA]    = a0.y;
            As[kqA*4+2][rowA]    = a0.z; As[kqA*4+3][rowA]    = a0.w;
            As[kqA*4+0][rowA+64] = a1.x; As[kqA*4+1][rowA+64] = a1.y;
            As[kqA*4+2][rowA+64] = a1.z; As[kqA*4+3][rowA+64] = a1.w;

            float4 b0 = *(const float4*)(xb + (size_t)(kc + kB)     * L_ + l0 + l4B*4);
            float4 b1 = *(const float4*)(xb + (size_t)(kc + kB + 8) * L_ + l0 + l4B*4);
            *(float4*)&Bs[kB][l4B*4]     = b0;
            *(float4*)&Bs[kB + 8][l4B*4] = b1;
        }
        __syncthreads();
        #pragma unroll
        for (int kk = 0; kk < 16; kk++) {
            float4 a0 = *(const float4*)&As[kk][ty*4];
            float4 a1 = *(const float4*)&As[kk][ty*4 + 64];
            float4 b0 = *(const float4*)&Bs[kk][tx*4];
            float4 b1 = *(const float4*)&Bs[kk][tx*4 + 64];
            const float a[2][4] = {{a0.x,a0.y,a0.z,a0.w},{a1.x,a1.y,a1.z,a1.w}};
            const float bb[2][4] = {{b0.x,b0.y,b0.z,b0.w},{b1.x,b1.y,b1.z,b1.w}};
            #pragma unroll
            for (int ai = 0; ai < 2; ai++)
                #pragma unroll
                for (int bi = 0; bi < 2; bi++)
                    #pragma unroll
                    for (int i = 0; i < 4; i++)
                        #pragma unroll
                        for (int j = 0; j < 4; j++)
                            acc[ai][bi][i][j] += a[ai][i] * bb[bi][j];
        }
        __syncthreads();
    }

    // Epilogue: add bias, scatter to q/k/v scratch (float4 stores)
    #pragma unroll
    for (int ai = 0; ai < 2; ai++)
        #pragma unroll
        for (int i = 0; i < 4; i++) {
            const int r = r0 + ai*64 + ty*4 + i;
            float bias; float* dst;
            if (r < 64)       { bias = bq[r];      dst = g_q + ((size_t)b*D_ + r)       * L_; }
            else if (r < 128) { bias = bk[r-64];   dst = g_k + ((size_t)b*D_ + (r-64))  * L_; }
            else              { bias = bv[r-128];  dst = g_v + ((size_t)b*C_ + (r-128)) * L_; }
            #pragma unroll
            for (int bi = 0; bi < 2; bi++) {
                float4 o;
                o.x = acc[ai][bi][i][0] + bias;
                o.y = acc[ai][bi][i][1] + bias;
                o.z = acc[ai][bi][i][2] + bias;
                o.w = acc[ai][bi][i][3] + bias;
                *(float4*)(dst + l0 + bi*64 + tx*4) = o;
            }
        }
}

// ===========================================================================
// Kernel 2: energy[b,l,m] = sum_d q[b,d,l]*k[b,d,m], lower-tri tiles only.
// 128x128 tile, BK=32 (two passes over D=64). Writes raw energy into att.
// ===========================================================================
__global__ __launch_bounds__(256) void energy_kernel(float* __restrict__ att)
{
    const int b  = blockIdx.z;
    const int lt = blockIdx.y;
    const int mt = blockIdx.x;
    if (mt > lt) return;
    const int l0 = lt * 128, m0 = mt * 128;
    const int tid = threadIdx.x;
    const int tx = tid & 15, ty = tid >> 4;

    __shared__ __align__(16) float Qs[32][132];   // [d][l]
    __shared__ __align__(16) float Ks[32][132];   // [d][m]

    const float* qb = g_q + (size_t)b * D_ * L_;
    const float* kb = g_k + (size_t)b * D_ * L_;

    float acc[2][2][4][4] = {};

    #pragma unroll
    for (int kc = 0; kc < 64; kc += 32) {
        // Load 32x128 Q and K slabs, direct coalesced (l contiguous)
        #pragma unroll
        for (int it = 0; it < 4; it++) {
            const int f  = tid + it * 256;       // 0..1023
            const int d  = f >> 5;               // 0..31
            const int l4 = f & 31;
            *(float4*)&Qs[d][l4*4] = *(const float4*)(qb + (size_t)(kc + d) * L_ + l0 + l4*4);
            *(float4*)&Ks[d][l4*4] = *(const float4*)(kb + (size_t)(kc + d) * L_ + m0 + l4*4);
        }
        __syncthreads();
        #pragma unroll 8
        for (int kk = 0; kk < 32; kk++) {
            float4 a0 = *(const float4*)&Qs[kk][ty*4];
            float4 a1 = *(const float4*)&Qs[kk][ty*4 + 64];
            float4 b0 = *(const float4*)&Ks[kk][tx*4];
            float4 b1 = *(const float4*)&Ks[kk][tx*4 + 64];
            const float a[2][4] = {{a0.x,a0.y,a0.z,a0.w},{a1.x,a1.y,a1.z,a1.w}};
            const float bb[2][4] = {{b0.x,b0.y,b0.z,b0.w},{b1.x,b1.y,b1.z,b1.w}};
            #pragma unroll
            for (int ai = 0; ai < 2; ai++)
                #pragma unroll
                for (int bi = 0; bi < 2; bi++)
                    #pragma unroll
                    for (int i = 0; i < 4; i++)
                        #pragma unroll
                        for (int j = 0; j < 4; j++)
                            acc[ai][bi][i][j] += a[ai][i] * bb[bi][j];
        }
        __syncthreads();
    }

    float* ab = att + (size_t)b * L_ * L_;
    #pragma unroll
    for (int ai = 0; ai < 2; ai++)
        #pragma unroll
        for (int i = 0; i < 4; i++) {
            const int l = l0 + ai*64 + ty*4 + i;
            #pragma unroll
            for (int bi = 0; bi < 2; bi++) {
                float4 o;
                o.x = acc[ai][bi][i][0]; o.y = acc[ai][bi][i][1];
                o.z = acc[ai][bi][i][2]; o.w = acc[ai][bi][i][3];
                *(float4*)(ab + (size_t)l * L_ + m0 + bi*64 + tx*4) = o;
            }
        }
}

// ===========================================================================
// Kernel 3: register-resident causal softmax (in-place over att).
// Each block handles one row; 8 floats/thread in registers, float4 I/O.
// ===========================================================================
__device__ __forceinline__ float block_reduce8(float v, float* red, bool is_max)
{
    #pragma unroll
    for (int o = 16; o > 0; o >>= 1) {
        const float t = __shfl_xor_sync(0xffffffffu, v, o);
        v = is_max ? fmaxf(v, t) : (v + t);
    }
    const int w = threadIdx.x >> 5;
    if ((threadIdx.x & 31) == 0) red[w] = v;
    __syncthreads();
    if (threadIdx.x < 32) {
        float t = (threadIdx.x < 8) ? red[threadIdx.x] : (is_max ? -INFINITY : 0.0f);
        #pragma unroll
        for (int o = 4; o > 0; o >>= 1) {
            const float u = __shfl_xor_sync(0xffffffffu, t, o);
            t = is_max ? fmaxf(t, u) : (t + u);
        }
        if (threadIdx.x == 0) red[0] = t;
    }
    __syncthreads();
    const float r = red[0];
    __syncthreads();
    return r;
}

__global__ __launch_bounds__(256) void softmax_kernel(
    float* __restrict__ att, const unsigned char* __restrict__ dmask)
{
    const int l = blockIdx.x;
    const int b = blockIdx.y;
    const int tid = threadIdx.x;

    __shared__ float red[8];

    float* arow = att + ((size_t)b * L_ + l) * L_;
    const uchar4* mrow = (const uchar4*)(dmask + ((size_t)b * L_ + l) * L_);
    const int n = l + 1;

    float v[8];
    float lmax = -INFINITY;
    #pragma unroll
    for (int it = 0; it < 2; it++) {
        const int j = tid + it * 256;          // float4 index 0..511
        const int base = j * 4;
        float4 e4 = ((const float4*)arow)[j];
        uchar4 m4 = mrow[j];
        v[it*4+0] = (base+0 < n && !m4.x) ? e4.x : -INFINITY;
        v[it*4+1] = (base+1 < n && !m4.y) ? e4.y : -INFINITY;
        v[it*4+2] = (base+2 < n && !m4.z) ? e4.z : -INFINITY;
        v[it*4+3] = (base+3 < n && !m4.w) ? e4.w : -INFINITY;
        #pragma unroll
        for (int c = 0; c < 4; c++) lmax = fmaxf(lmax, v[it*4+c]);
    }
    const float rmax = block_reduce8(lmax, red, true);

    float lsum = 0.0f;
    #pragma unroll
    for (int c = 0; c < 8; c++) {
        const float p = (v[c] == -INFINITY) ? 0.0f : __expf(v[c] - rmax);
        v[c] = p;
        lsum += p;
    }
    const float rsum = block_reduce8(lsum, red, false);
    const float inv = 1.0f / rsum;

    #pragma unroll
    for (int it = 0; it < 2; it++) {
        const int j = tid + it * 256;
        float4 o;
        o.x = v[it*4+0] * inv; o.y = v[it*4+1] * inv;
        o.z = v[it*4+2] * inv; o.w = v[it*4+3] * inv;
        ((float4*)arow)[j] = o;
    }
}

// ===========================================================================
// Kernel 4: out[b,c,m] = sum_l v[b,c,l] * att[b,m,l].
// 128x128 tile, 8x8 micro-tile, BK=16. Causal K-truncation: l < m0 + 128.
// ===========================================================================
__global__ __launch_bounds__(256) void out_gemm_kernel(
    const float* __restrict__ att, float* __restrict__ out)
{
    const int b  = blockIdx.z;
    const int c0 = blockIdx.y * 128;
    const int m0 = blockIdx.x * 128;
    const int tid = threadIdx.x;
    const int tx = tid & 15, ty = tid >> 4;

    __shared__ __align__(16) float As[16][132];   // [k=l][c-row]
    __shared__ __align__(16) float Bs[16][132];   // [k=l][m-row]

    const float* vb = g_v + (size_t)b * C_ * L_;
    const float* ab = att + (size_t)b * L_ * L_;

    // Per-thread load assignment (both operands are k-contiguous -> transpose)
    const int rowT = tid >> 2;        // 0..63
    const int kqT  = tid & 3;
    const float* aptr0 = vb + (size_t)(c0 + rowT)      * L_ + kqT * 4;
    const float* aptr1 = vb + (size_t)(c0 + rowT + 64) * L_ + kqT * 4;
    const float* bptr0 = ab + (size_t)(m0 + rowT)      * L_ + kqT * 4;
    const float* bptr1 = ab + (size_t)(m0 + rowT + 64) * L_ + kqT * 4;

    float acc[2][2][4][4] = {};
    const int kend = m0 + 128;        // att[m, l] = 0 for l > m

    for (int lc = 0; lc < kend; lc += 16) {
        {
            float4 a0 = *(const float4*)(aptr0 + lc);
            float4 a1 = *(const float4*)(aptr1 + lc);
            As[kqT*4+0][rowT]    = a0.x; As[kqT*4+1][rowT]    = a0.y;
            As[kqT*4+2][rowT]    = a0.z; As[kqT*4+3][rowT]    = a0.w;
            As[kqT*4+0][rowT+64] = a1.x; As[kqT*4+1][rowT+64] = a1.y;
            As[kqT*4+2][rowT+64] = a1.z; As[kqT*4+3][rowT+64] = a1.w;

            float4 b0 = *(const float4*)(bptr0 + lc);
            float4 b1 = *(const float4*)(bptr1 + lc);
            Bs[kqT*4+0][rowT]    = b0.x; Bs[kqT*4+1][rowT]    = b0.y;
            Bs[kqT*4+2][rowT]    = b0.z; Bs[kqT*4+3][rowT]    = b0.w;
            Bs[kqT*4+0][rowT+64] = b1.x; Bs[kqT*4+1][rowT+64] = b1.y;
            Bs[kqT*4+2][rowT+64] = b1.z; Bs[kqT*4+3][rowT+64] = b1.w;
        }
        __syncthreads();
        #pragma unroll
        for (int kk = 0; kk < 16; kk++) {
            float4 a0 = *(const float4*)&As[kk][ty*4];
            float4 a1 = *(const float4*)&As[kk][ty*4 + 64];
            float4 b0 = *(const float4*)&Bs[kk][tx*4];
            float4 b1 = *(const float4*)&Bs[kk][tx*4 + 64];
            const float a[2][4] = {{a0.x,a0.y,a0.z,a0.w},{a1.x,a1.y,a1.z,a1.w}};
            const float bb[2][4] = {{b0.x,b0.y,b0.z,b0.w},{b1.x,b1.y,b1.z,b1.w}};
            #pragma unroll
            for (int ai = 0; ai < 2; ai++)
                #pragma unroll
                for (int bi = 0; bi < 2; bi++)
                    #pragma unroll
                    for (int i = 0; i < 4; i++)
                        #pragma unroll
                        for (int j = 0; j < 4; j++)
                            acc[ai][bi][i][j] += a[ai][i] * bb[bi][j];
        }
        __syncthreads();
    }

    float* ob = out + (size_t)b * C_ * L_;
    #pragma unroll
    for (int ai = 0; ai < 2; ai++)
        #pragma unroll
        for (int i = 0; i < 4; i++) {
            const int c = c0 + ai*64 + ty*4 + i;
            #pragma unroll
            for (int bi = 0; bi < 2; bi++) {
                float4 o;
                o.x = acc[ai][bi][i][0]; o.y = acc[ai][bi][i][1];
                o.z = acc[ai][bi][i][2]; o.w = acc[ai][bi][i][3];
                *(float4*)(ob + (size_t)c * L_ + m0 + bi*64 + tx*4) = o;
            }
        }
}

// ===========================================================================
extern "C" void kernel_launch(void* const* d_in, const int* in_sizes, int n_in,
                              void* d_out, int out_size)
{
    (void)in_sizes; (void)n_in; (void)out_size;
    const float* x          = (const float*)d_in[0];
    const unsigned char* dm = (const unsigned char*)d_in[1];
    const float* Wq = (const float*)d_in[2];
    const float* bq = (const float*)d_in[3];
    const float* Wk = (const float*)d_in[4];
    const float* bk = (const float*)d_in[5];
    const float* Wv = (const float*)d_in[6];
    const float* bv = (const float*)d_in[7];

    float* out = (float*)d_out;                      // (B, C, L)
    float* att = out + (size_t)B_ * C_ * L_;         // (B, L, L)

    qkv_proj_kernel<<<dim3(L_/128, 640/128, B_), 256>>>(x, Wq, bq, Wk, bk, Wv, bv);
    energy_kernel  <<<dim3(L_/128, L_/128, B_), 256>>>(att);
    softmax_kernel <<<dim3(L_, B_), 256>>>(att, dm);
    out_gemm_kernel<<<dim3(L_/128, C_/128, B_), 256>>>(att, out);
}

// round 5
// speedup vs baseline: 1.8868x; 1.6549x over previous
#include <cuda_runtime.h>
#include <math.h>
#include <stdint.h>

#define B_ 8
#define C_ 512
#define L_ 2048
#define D_ 64

// Scratch (allocation-free rule: device globals)
__device__ float g_q[B_*D_*L_];          // (b, d, l)
__device__ float g_k[B_*D_*L_];          // (b, d, l)
__device__ float g_v[(size_t)B_*C_*L_];  // (b, c, l)

__device__ __forceinline__ uint32_t f2tf32(float f) {
    uint32_t u;
    asm("cvt.rna.tf32.f32 %0, %1;" : "=r"(u) : "f"(f));
    return u;
}

// ===========================================================================
// Kernel 1: fused QKV projection (fp32 SIMT, proven in R2)
// ===========================================================================
__device__ __forceinline__ const float* w_row_ptr(
    int r, const float* Wq, const float* Wk, const float* Wv)
{
    return (r < 64)  ? Wq + (size_t)r * C_
         : (r < 128) ? Wk + (size_t)(r - 64) * C_
                     : Wv + (size_t)(r - 128) * C_;
}

__global__ __launch_bounds__(256) void qkv_proj_kernel(
    const float* __restrict__ x,
    const float* __restrict__ Wq, const float* __restrict__ bq,
    const float* __restrict__ Wk, const float* __restrict__ bk,
    const float* __restrict__ Wv, const float* __restrict__ bv)
{
    const int b  = blockIdx.z;
    const int r0 = blockIdx.y * 128;
    const int l0 = blockIdx.x * 128;
    const int tid = threadIdx.x;
    const int tx = tid & 15, ty = tid >> 4;

    __shared__ __align__(16) float As[16][132];
    __shared__ __align__(16) float Bs[16][132];

    const float* xb = x + (size_t)b * C_ * L_;

    const int rowA = tid >> 2;
    const int kqA  = tid & 3;
    const float* aptr0 = w_row_ptr(r0 + rowA,      Wq, Wk, Wv) + kqA * 4;
    const float* aptr1 = w_row_ptr(r0 + rowA + 64, Wq, Wk, Wv) + kqA * 4;

    const int kB  = tid >> 5;
    const int l4B = tid & 31;

    float acc[2][2][4][4] = {};

    for (int kc = 0; kc < C_; kc += 16) {
        {
            float4 a0 = *(const float4*)(aptr0 + kc);
            float4 a1 = *(const float4*)(aptr1 + kc);
            As[kqA*4+0][rowA]    = a0.x; As[kqA*4+1][rowA]    = a0.y;
            As[kqA*4+2][rowA]    = a0.z; As[kqA*4+3][rowA]    = a0.w;
            As[kqA*4+0][rowA+64] = a1.x; As[kqA*4+1][rowA+64] = a1.y;
            As[kqA*4+2][rowA+64] = a1.z; As[kqA*4+3][rowA+64] = a1.w;

            float4 b0 = *(const float4*)(xb + (size_t)(kc + kB)     * L_ + l0 + l4B*4);
            float4 b1 = *(const float4*)(xb + (size_t)(kc + kB + 8) * L_ + l0 + l4B*4);
            *(float4*)&Bs[kB][l4B*4]     = b0;
            *(float4*)&Bs[kB + 8][l4B*4] = b1;
        }
        __syncthreads();
        #pragma unroll
        for (int kk = 0; kk < 16; kk++) {
            float4 a0 = *(const float4*)&As[kk][ty*4];
            float4 a1 = *(const float4*)&As[kk][ty*4 + 64];
            float4 b0 = *(const float4*)&Bs[kk][tx*4];
            float4 b1 = *(const float4*)&Bs[kk][tx*4 + 64];
            const float a[2][4]  = {{a0.x,a0.y,a0.z,a0.w},{a1.x,a1.y,a1.z,a1.w}};
            const float bb[2][4] = {{b0.x,b0.y,b0.z,b0.w},{b1.x,b1.y,b1.z,b1.w}};
            #pragma unroll
            for (int ai = 0; ai < 2; ai++)
                #pragma unroll
                for (int bi = 0; bi < 2; bi++)
                    #pragma unroll
                    for (int i = 0; i < 4; i++)
                        #pragma unroll
                        for (int j = 0; j < 4; j++)
                            acc[ai][bi][i][j] += a[ai][i] * bb[bi][j];
        }
        __syncthreads();
    }

    #pragma unroll
    for (int ai = 0; ai < 2; ai++)
        #pragma unroll
        for (int i = 0; i < 4; i++) {
            const int r = r0 + ai*64 + ty*4 + i;
            float bias; float* dst;
            if (r < 64)       { bias = bq[r];      dst = g_q + ((size_t)b*D_ + r)       * L_; }
            else if (r < 128) { bias = bk[r-64];   dst = g_k + ((size_t)b*D_ + (r-64))  * L_; }
            else              { bias = bv[r-128];  dst = g_v + ((size_t)b*C_ + (r-128)) * L_; }
            #pragma unroll
            for (int bi = 0; bi < 2; bi++) {
                float4 o;
                o.x = acc[ai][bi][i][0] + bias;
                o.y = acc[ai][bi][i][1] + bias;
                o.z = acc[ai][bi][i][2] + bias;
                o.w = acc[ai][bi][i][3] + bias;
                *(float4*)(dst + l0 + bi*64 + tx*4) = o;
            }
        }
}

// ===========================================================================
// Kernel 2: energy (fp32 SIMT, proven in R2)
// ===========================================================================
__global__ __launch_bounds__(256) void energy_kernel(float* __restrict__ att)
{
    const int b  = blockIdx.z;
    const int lt = blockIdx.y;
    const int mt = blockIdx.x;
    if (mt > lt) return;
    const int l0 = lt * 128, m0 = mt * 128;
    const int tid = threadIdx.x;
    const int tx = tid & 15, ty = tid >> 4;

    __shared__ __align__(16) float Qs[32][132];
    __shared__ __align__(16) float Ks[32][132];

    const float* qb = g_q + (size_t)b * D_ * L_;
    const float* kb = g_k + (size_t)b * D_ * L_;

    float acc[2][2][4][4] = {};

    #pragma unroll
    for (int kc = 0; kc < 64; kc += 32) {
        #pragma unroll
        for (int it = 0; it < 4; it++) {
            const int f  = tid + it * 256;
            const int d  = f >> 5;
            const int l4 = f & 31;
            *(float4*)&Qs[d][l4*4] = *(const float4*)(qb + (size_t)(kc + d) * L_ + l0 + l4*4);
            *(float4*)&Ks[d][l4*4] = *(const float4*)(kb + (size_t)(kc + d) * L_ + m0 + l4*4);
        }
        __syncthreads();
        #pragma unroll 8
        for (int kk = 0; kk < 32; kk++) {
            float4 a0 = *(const float4*)&Qs[kk][ty*4];
            float4 a1 = *(const float4*)&Qs[kk][ty*4 + 64];
            float4 b0 = *(const float4*)&Ks[kk][tx*4];
            float4 b1 = *(const float4*)&Ks[kk][tx*4 + 64];
            const float a[2][4]  = {{a0.x,a0.y,a0.z,a0.w},{a1.x,a1.y,a1.z,a1.w}};
            const float bb[2][4] = {{b0.x,b0.y,b0.z,b0.w},{b1.x,b1.y,b1.z,b1.w}};
            #pragma unroll
            for (int ai = 0; ai < 2; ai++)
                #pragma unroll
                for (int bi = 0; bi < 2; bi++)
                    #pragma unroll
                    for (int i = 0; i < 4; i++)
                        #pragma unroll
                        for (int j = 0; j < 4; j++)
                            acc[ai][bi][i][j] += a[ai][i] * bb[bi][j];
        }
        __syncthreads();
    }

    float* ab = att + (size_t)b * L_ * L_;
    #pragma unroll
    for (int ai = 0; ai < 2; ai++)
        #pragma unroll
        for (int i = 0; i < 4; i++) {
            const int l = l0 + ai*64 + ty*4 + i;
            #pragma unroll
            for (int bi = 0; bi < 2; bi++) {
                float4 o;
                o.x = acc[ai][bi][i][0]; o.y = acc[ai][bi][i][1];
                o.z = acc[ai][bi][i][2]; o.w = acc[ai][bi][i][3];
                *(float4*)(ab + (size_t)l * L_ + m0 + bi*64 + tx*4) = o;
            }
        }
}

// ===========================================================================
// Kernel 3: register-resident causal softmax (proven in R2)
// ===========================================================================
__device__ __forceinline__ float block_reduce8(float v, float* red, bool is_max)
{
    #pragma unroll
    for (int o = 16; o > 0; o >>= 1) {
        const float t = __shfl_xor_sync(0xffffffffu, v, o);
        v = is_max ? fmaxf(v, t) : (v + t);
    }
    const int w = threadIdx.x >> 5;
    if ((threadIdx.x & 31) == 0) red[w] = v;
    __syncthreads();
    if (threadIdx.x < 32) {
        float t = (threadIdx.x < 8) ? red[threadIdx.x] : (is_max ? -INFINITY : 0.0f);
        #pragma unroll
        for (int o = 4; o > 0; o >>= 1) {
            const float u = __shfl_xor_sync(0xffffffffu, t, o);
            t = is_max ? fmaxf(t, u) : (t + u);
        }
        if (threadIdx.x == 0) red[0] = t;
    }
    __syncthreads();
    const float r = red[0];
    __syncthreads();
    return r;
}

__global__ __launch_bounds__(256) void softmax_kernel(
    float* __restrict__ att, const unsigned char* __restrict__ dmask)
{
    const int l = blockIdx.x;
    const int b = blockIdx.y;
    const int tid = threadIdx.x;

    __shared__ float red[8];

    float* arow = att + ((size_t)b * L_ + l) * L_;
    const uchar4* mrow = (const uchar4*)(dmask + ((size_t)b * L_ + l) * L_);
    const int n = l + 1;

    float v[8];
    float lmax = -INFINITY;
    #pragma unroll
    for (int it = 0; it < 2; it++) {
        const int j = tid + it * 256;
        const int base = j * 4;
        float4 e4 = ((const float4*)arow)[j];
        uchar4 m4 = mrow[j];
        v[it*4+0] = (base+0 < n && !m4.x) ? e4.x : -INFINITY;
        v[it*4+1] = (base+1 < n && !m4.y) ? e4.y : -INFINITY;
        v[it*4+2] = (base+2 < n && !m4.z) ? e4.z : -INFINITY;
        v[it*4+3] = (base+3 < n && !m4.w) ? e4.w : -INFINITY;
        #pragma unroll
        for (int c = 0; c < 4; c++) lmax = fmaxf(lmax, v[it*4+c]);
    }
    const float rmax = block_reduce8(lmax, red, true);

    float lsum = 0.0f;
    #pragma unroll
    for (int c = 0; c < 8; c++) {
        const float p = (v[c] == -INFINITY) ? 0.0f : __expf(v[c] - rmax);
        v[c] = p;
        lsum += p;
    }
    const float rsum = block_reduce8(lsum, red, false);
    const float inv = 1.0f / rsum;

    #pragma unroll
    for (int it = 0; it < 2; it++) {
        const int j = tid + it * 256;
        float4 o;
        o.x = v[it*4+0] * inv; o.y = v[it*4+1] * inv;
        o.z = v[it*4+2] * inv; o.w = v[it*4+3] * inv;
        ((float4*)arow)[j] = o;
    }
}

// ===========================================================================
// Kernel 4: out[b,c,m] = sum_l v[b,c,l] * att[b,m,l]
// tf32 mma.sync.m16n8k8 (target-agnostic PTX; tensor pipe).
// 128(c) x 128(m) block, 8 warps (warp_m 0..1 x warp_n 0..3), 64x32 warp tile,
// BK=32, smem [row][k] with stride 36 (conflict-free fragment gather).
// Causal: K loop truncated at l < m0 + 128 (att is exact 0 above diagonal).
// ===========================================================================
__global__ __launch_bounds__(256, 2) void out_gemm_mma_kernel(
    const float* __restrict__ att, float* __restrict__ out)
{
    __shared__ __align__(16) float As[128][36];   // V tile   [c-row][k=l]
    __shared__ __align__(16) float Bs[128][36];   // Att tile [m-row][k=l]

    const int b  = blockIdx.z;
    const int m0 = blockIdx.x * 128;
    const int c0 = blockIdx.y * 128;
    const int tid  = threadIdx.x;
    const int warp = tid >> 5;
    const int lane = tid & 31;
    const int warp_m = (warp & 1) * 64;   // c-offset within block
    const int warp_n = (warp >> 1) * 32;  // m-offset within block
    const int r  = lane >> 2;             // 0..7
    const int c4 = lane & 3;              // 0..3

    const float* vb = g_v + (size_t)b * C_ * L_;
    const float* ab = att + (size_t)b * L_ * L_;

    const int rowL = tid >> 3;            // 0..31 (x4 -> 128 rows)
    const int q    = tid & 7;             // float4 slot within 32 k

    float acc[4][4][4] = {};              // [mt][nt][frag]

    const int kend = m0 + 128;
    for (int lc = 0; lc < kend; lc += 32) {
        // Load V/Att slabs, round to tf32 once here
        #pragma unroll
        for (int i = 0; i < 4; i++) {
            const int rr = rowL + i * 32;
            float4 a4 = *(const float4*)(vb + (size_t)(c0 + rr) * L_ + lc + q * 4);
            float4 b4 = *(const float4*)(ab + (size_t)(m0 + rr) * L_ + lc + q * 4);
            uint4 au, bu;
            au.x = f2tf32(a4.x); au.y = f2tf32(a4.y); au.z = f2tf32(a4.z); au.w = f2tf32(a4.w);
            bu.x = f2tf32(b4.x); bu.y = f2tf32(b4.y); bu.z = f2tf32(b4.z); bu.w = f2tf32(b4.w);
            *(uint4*)&As[rr][q * 4] = au;
            *(uint4*)&Bs[rr][q * 4] = bu;
        }
        __syncthreads();

        #pragma unroll
        for (int ks = 0; ks < 4; ks++) {
            const int k8 = ks * 8;
            uint32_t af[4][4], bf[4][2];
            #pragma unroll
            for (int mt = 0; mt < 4; mt++) {
                const int ar = warp_m + mt * 16 + r;
                af[mt][0] = __float_as_uint(As[ar    ][k8 + c4]);
                af[mt][1] = __float_as_uint(As[ar + 8][k8 + c4]);
                af[mt][2] = __float_as_uint(As[ar    ][k8 + c4 + 4]);
                af[mt][3] = __float_as_uint(As[ar + 8][k8 + c4 + 4]);
            }
            #pragma unroll
            for (int nt = 0; nt < 4; nt++) {
                const int br = warp_n + nt * 8 + r;
                bf[nt][0] = __float_as_uint(Bs[br][k8 + c4]);
                bf[nt][1] = __float_as_uint(Bs[br][k8 + c4 + 4]);
            }
            #pragma unroll
            for (int mt = 0; mt < 4; mt++)
                #pragma unroll
                for (int nt = 0; nt < 4; nt++)
                    asm volatile(
                        "mma.sync.aligned.m16n8k8.row.col.f32.tf32.tf32.f32 "
                        "{%0,%1,%2,%3}, {%4,%5,%6,%7}, {%8,%9}, {%0,%1,%2,%3};"
                        : "+f"(acc[mt][nt][0]), "+f"(acc[mt][nt][1]),
                          "+f"(acc[mt][nt][2]), "+f"(acc[mt][nt][3])
                        : "r"(af[mt][0]), "r"(af[mt][1]), "r"(af[mt][2]), "r"(af[mt][3]),
                          "r"(bf[nt][0]), "r"(bf[nt][1]));
        }
        __syncthreads();
    }

    // Epilogue: direct STG.64 (c0,c1 are adjacent columns)
    float* ob = out + (size_t)b * C_ * L_;
    #pragma unroll
    for (int mt = 0; mt < 4; mt++) {
        const int crow = c0 + warp_m + mt * 16 + r;
        #pragma unroll
        for (int nt = 0; nt < 4; nt++) {
            const int mcol = m0 + warp_n + nt * 8 + c4 * 2;
            float2 o0 = make_float2(acc[mt][nt][0], acc[mt][nt][1]);
            float2 o1 = make_float2(acc[mt][nt][2], acc[mt][nt][3]);
            *(float2*)(ob + (size_t)crow       * L_ + mcol) = o0;
            *(float2*)(ob + (size_t)(crow + 8) * L_ + mcol) = o1;
        }
    }
}

// ===========================================================================
extern "C" void kernel_launch(void* const* d_in, const int* in_sizes, int n_in,
                              void* d_out, int out_size)
{
    (void)in_sizes; (void)n_in; (void)out_size;
    const float* x          = (const float*)d_in[0];
    const unsigned char* dm = (const unsigned char*)d_in[1];
    const float* Wq = (const float*)d_in[2];
    const float* bq = (const float*)d_in[3];
    const float* Wk = (const float*)d_in[4];
    const float* bk = (const float*)d_in[5];
    const float* Wv = (const float*)d_in[6];
    const float* bv = (const float*)d_in[7];

    float* out = (float*)d_out;                      // (B, C, L)
    float* att = out + (size_t)B_ * C_ * L_;         // (B, L, L)

    qkv_proj_kernel<<<dim3(L_/128, 640/128, B_), 256>>>(x, Wq, bq, Wk, bk, Wv, bv);
    energy_kernel  <<<dim3(L_/128, L_/128, B_), 256>>>(att);
    softmax_kernel <<<dim3(L_, B_), 256>>>(att, dm);
    out_gemm_mma_kernel<<<dim3(L_/128, C_/128, B_), 256>>>(att, out);
}

// round 6
// speedup vs baseline: 2.6748x; 1.4177x over previous
#include <cuda_runtime.h>
#include <math.h>
#include <stdint.h>

#define B_ 8
#define C_ 512
#define L_ 2048
#define D_ 64

// Scratch (allocation-free rule: device globals)
__device__ float g_q[B_*D_*L_];          // (b, d, l)
__device__ float g_k[B_*D_*L_];          // (b, d, l)
__device__ float g_v[(size_t)B_*C_*L_];  // (b, c, l)

__device__ __forceinline__ uint32_t f2tf32(float f) {
    uint32_t u;
    asm("cvt.rna.tf32.f32 %0, %1;" : "=r"(u) : "f"(f));
    return u;
}

#define MMA_TF32(acc, af, bf)                                                  \
    asm volatile(                                                              \
        "mma.sync.aligned.m16n8k8.row.col.f32.tf32.tf32.f32 "                  \
        "{%0,%1,%2,%3}, {%4,%5,%6,%7}, {%8,%9}, {%0,%1,%2,%3};"                \
        : "+f"((acc)[0]), "+f"((acc)[1]), "+f"((acc)[2]), "+f"((acc)[3])       \
        : "r"((af)[0]), "r"((af)[1]), "r"((af)[2]), "r"((af)[3]),              \
          "r"((bf)[0]), "r"((bf)[1]))

__device__ __forceinline__ const float* w_row_ptr(
    int r, const float* Wq, const float* Wk, const float* Wv)
{
    return (r < 64)  ? Wq + (size_t)r * C_
         : (r < 128) ? Wk + (size_t)(r - 64) * C_
                     : Wv + (size_t)(r - 128) * C_;
}

// ===========================================================================
// Kernel 1: fused QKV projection, tf32 mma.
// Out rows R=640 (q 0..63, k 64..127, v 128..639), cols L, K=C=512.
// Block 128x128, 8 warps (warp_m 2 x warp_n 4), BK=32.
// As [row][k] stride 36 (weights, k-contiguous). Bs [k][l] stride 136 (x).
// ===========================================================================
__global__ __launch_bounds__(256, 2) void qkv_proj_mma_kernel(
    const float* __restrict__ x,
    const float* __restrict__ Wq, const float* __restrict__ bq,
    const float* __restrict__ Wk, const float* __restrict__ bk,
    const float* __restrict__ Wv, const float* __restrict__ bv)
{
    __shared__ __align__(16) float As[128][36];
    __shared__ __align__(16) float Bs[32][136];

    const int b  = blockIdx.z;
    const int l0 = blockIdx.x * 128;
    const int r0 = blockIdx.y * 128;
    const int tid  = threadIdx.x;
    const int warp = tid >> 5;
    const int lane = tid & 31;
    const int warp_m = (warp & 1) * 64;   // row offset (W rows)
    const int warp_n = (warp >> 1) * 32;  // col offset (l)
    const int r  = lane >> 2;
    const int c4 = lane & 3;

    const float* xb = x + (size_t)b * C_ * L_;

    const int rowL = tid >> 3;            // 0..31 (x4 -> 128 rows of A)
    const int q8   = tid & 7;             // float4 slot within 32 k

    float acc[4][4][4] = {};

    for (int kc = 0; kc < C_; kc += 32) {
        // A: weights, k-contiguous float4
        #pragma unroll
        for (int i = 0; i < 4; i++) {
            const int rr = rowL + i * 32;
            const float* wp = w_row_ptr(r0 + rr, Wq, Wk, Wv);
            float4 a4 = *(const float4*)(wp + kc + q8 * 4);
            uint4 au;
            au.x = f2tf32(a4.x); au.y = f2tf32(a4.y);
            au.z = f2tf32(a4.z); au.w = f2tf32(a4.w);
            *(uint4*)&As[rr][q8 * 4] = au;
        }
        // B: x slab [k][l], l-contiguous float4
        #pragma unroll
        for (int it = 0; it < 4; it++) {
            const int f  = tid + it * 256;
            const int d  = f >> 5;
            const int l4 = f & 31;
            float4 b4 = *(const float4*)(xb + (size_t)(kc + d) * L_ + l0 + l4 * 4);
            uint4 bu;
            bu.x = f2tf32(b4.x); bu.y = f2tf32(b4.y);
            bu.z = f2tf32(b4.z); bu.w = f2tf32(b4.w);
            *(uint4*)&Bs[d][l4 * 4] = bu;
        }
        __syncthreads();

        #pragma unroll
        for (int ks = 0; ks < 4; ks++) {
            const int k8 = ks * 8;
            uint32_t af[4][4], bf[4][2];
            #pragma unroll
            for (int mt = 0; mt < 4; mt++) {
                const int ar = warp_m + mt * 16 + r;
                af[mt][0] = __float_as_uint(As[ar    ][k8 + c4]);
                af[mt][1] = __float_as_uint(As[ar + 8][k8 + c4]);
                af[mt][2] = __float_as_uint(As[ar    ][k8 + c4 + 4]);
                af[mt][3] = __float_as_uint(As[ar + 8][k8 + c4 + 4]);
            }
            #pragma unroll
            for (int nt = 0; nt < 4; nt++) {
                const int bn = warp_n + nt * 8 + r;
                bf[nt][0] = __float_as_uint(Bs[k8 + c4    ][bn]);
                bf[nt][1] = __float_as_uint(Bs[k8 + c4 + 4][bn]);
            }
            #pragma unroll
            for (int mt = 0; mt < 4; mt++)
                #pragma unroll
                for (int nt = 0; nt < 4; nt++)
                    MMA_TF32(acc[mt][nt], af[mt], bf[nt]);
        }
        __syncthreads();
    }

    // Epilogue: add bias, scatter to g_q/g_k/g_v (float2 stores)
    #pragma unroll
    for (int mt = 0; mt < 4; mt++) {
        #pragma unroll
        for (int half = 0; half < 2; half++) {
            const int rr = r0 + warp_m + mt * 16 + r + half * 8;
            float bias; float* dst;
            if (rr < 64)       { bias = bq[rr];      dst = g_q + ((size_t)b*D_ + rr)       * L_; }
            else if (rr < 128) { bias = bk[rr-64];   dst = g_k + ((size_t)b*D_ + (rr-64))  * L_; }
            else               { bias = bv[rr-128];  dst = g_v + ((size_t)b*C_ + (rr-128)) * L_; }
            #pragma unroll
            for (int nt = 0; nt < 4; nt++) {
                const int col = l0 + warp_n + nt * 8 + c4 * 2;
                float2 o;
                o.x = acc[mt][nt][half*2 + 0] + bias;
                o.y = acc[mt][nt][half*2 + 1] + bias;
                *(float2*)(dst + col) = o;
            }
        }
    }
}

// ===========================================================================
// Kernel 2: energy[b,l,m] = sum_d q[b,d,l]*k[b,d,m], tf32 mma, lower-tri only.
// Block 128(l) x 128(m), BK=32 (2 passes over D=64).
// Both operands in [d][*] stride-136 layout (conflict-free fragment gather).
// ===========================================================================
__global__ __launch_bounds__(256, 2) void energy_mma_kernel(float* __restrict__ att)
{
    __shared__ __align__(16) float Qs[32][136];
    __shared__ __align__(16) float Ks[32][136];

    const int b  = blockIdx.z;
    const int lt = blockIdx.y;
    const int mt_ = blockIdx.x;
    if (mt_ > lt) return;
    const int l0 = lt * 128, m0 = mt_ * 128;
    const int tid  = threadIdx.x;
    const int warp = tid >> 5;
    const int lane = tid & 31;
    const int warp_m = (warp & 1) * 64;   // l offset
    const int warp_n = (warp >> 1) * 32;  // m offset
    const int r  = lane >> 2;
    const int c4 = lane & 3;

    const float* qb = g_q + (size_t)b * D_ * L_;
    const float* kb = g_k + (size_t)b * D_ * L_;

    float acc[4][4][4] = {};

    #pragma unroll
    for (int kc = 0; kc < 64; kc += 32) {
        #pragma unroll
        for (int it = 0; it < 4; it++) {
            const int f  = tid + it * 256;
            const int d  = f >> 5;
            const int l4 = f & 31;
            float4 a4 = *(const float4*)(qb + (size_t)(kc + d) * L_ + l0 + l4 * 4);
            float4 b4 = *(const float4*)(kb + (size_t)(kc + d) * L_ + m0 + l4 * 4);
            uint4 au, bu;
            au.x = f2tf32(a4.x); au.y = f2tf32(a4.y); au.z = f2tf32(a4.z); au.w = f2tf32(a4.w);
            bu.x = f2tf32(b4.x); bu.y = f2tf32(b4.y); bu.z = f2tf32(b4.z); bu.w = f2tf32(b4.w);
            *(uint4*)&Qs[d][l4 * 4] = au;
            *(uint4*)&Ks[d][l4 * 4] = bu;
        }
        __syncthreads();

        #pragma unroll
        for (int ks = 0; ks < 4; ks++) {
            const int k8 = ks * 8;
            uint32_t af[4][4], bf[4][2];
            #pragma unroll
            for (int mt = 0; mt < 4; mt++) {
                const int al = warp_m + mt * 16 + r;
                af[mt][0] = __float_as_uint(Qs[k8 + c4    ][al]);
                af[mt][1] = __float_as_uint(Qs[k8 + c4    ][al + 8]);
                af[mt][2] = __float_as_uint(Qs[k8 + c4 + 4][al]);
                af[mt][3] = __float_as_uint(Qs[k8 + c4 + 4][al + 8]);
            }
            #pragma unroll
            for (int nt = 0; nt < 4; nt++) {
                const int bn = warp_n + nt * 8 + r;
                bf[nt][0] = __float_as_uint(Ks[k8 + c4    ][bn]);
                bf[nt][1] = __float_as_uint(Ks[k8 + c4 + 4][bn]);
            }
            #pragma unroll
            for (int mt = 0; mt < 4; mt++)
                #pragma unroll
                for (int nt = 0; nt < 4; nt++)
                    MMA_TF32(acc[mt][nt], af[mt], bf[nt]);
        }
        __syncthreads();
    }

    float* ab = att + (size_t)b * L_ * L_;
    #pragma unroll
    for (int mt = 0; mt < 4; mt++) {
        #pragma unroll
        for (int half = 0; half < 2; half++) {
            const int l = l0 + warp_m + mt * 16 + r + half * 8;
            #pragma unroll
            for (int nt = 0; nt < 4; nt++) {
                const int m = m0 + warp_n + nt * 8 + c4 * 2;
                float2 o;
                o.x = acc[mt][nt][half*2 + 0];
                o.y = acc[mt][nt][half*2 + 1];
                *(float2*)(ab + (size_t)l * L_ + m) = o;
            }
        }
    }
}

// ===========================================================================
// Kernel 3: register-resident causal softmax (proven in R2)
// ===========================================================================
__device__ __forceinline__ float block_reduce8(float v, float* red, bool is_max)
{
    #pragma unroll
    for (int o = 16; o > 0; o >>= 1) {
        const float t = __shfl_xor_sync(0xffffffffu, v, o);
        v = is_max ? fmaxf(v, t) : (v + t);
    }
    const int w = threadIdx.x >> 5;
    if ((threadIdx.x & 31) == 0) red[w] = v;
    __syncthreads();
    if (threadIdx.x < 32) {
        float t = (threadIdx.x < 8) ? red[threadIdx.x] : (is_max ? -INFINITY : 0.0f);
        #pragma unroll
        for (int o = 4; o > 0; o >>= 1) {
            const float u = __shfl_xor_sync(0xffffffffu, t, o);
            t = is_max ? fmaxf(t, u) : (t + u);
        }
        if (threadIdx.x == 0) red[0] = t;
    }
    __syncthreads();
    const float r = red[0];
    __syncthreads();
    return r;
}

__global__ __launch_bounds__(256) void softmax_kernel(
    float* __restrict__ att, const unsigned char* __restrict__ dmask)
{
    const int l = blockIdx.x;
    const int b = blockIdx.y;
    const int tid = threadIdx.x;

    __shared__ float red[8];

    float* arow = att + ((size_t)b * L_ + l) * L_;
    const uchar4* mrow = (const uchar4*)(dmask + ((size_t)b * L_ + l) * L_);
    const int n = l + 1;

    float v[8];
    float lmax = -INFINITY;
    #pragma unroll
    for (int it = 0; it < 2; it++) {
        const int j = tid + it * 256;
        const int base = j * 4;
        float4 e4 = ((const float4*)arow)[j];
        uchar4 m4 = mrow[j];
        v[it*4+0] = (base+0 < n && !m4.x) ? e4.x : -INFINITY;
        v[it*4+1] = (base+1 < n && !m4.y) ? e4.y : -INFINITY;
        v[it*4+2] = (base+2 < n && !m4.z) ? e4.z : -INFINITY;
        v[it*4+3] = (base+3 < n && !m4.w) ? e4.w : -INFINITY;
        #pragma unroll
        for (int c = 0; c < 4; c++) lmax = fmaxf(lmax, v[it*4+c]);
    }
    const float rmax = block_reduce8(lmax, red, true);

    float lsum = 0.0f;
    #pragma unroll
    for (int c = 0; c < 8; c++) {
        const float p = (v[c] == -INFINITY) ? 0.0f : __expf(v[c] - rmax);
        v[c] = p;
        lsum += p;
    }
    const float rsum = block_reduce8(lsum, red, false);
    const float inv = 1.0f / rsum;

    #pragma unroll
    for (int it = 0; it < 2; it++) {
        const int j = tid + it * 256;
        float4 o;
        o.x = v[it*4+0] * inv; o.y = v[it*4+1] * inv;
        o.z = v[it*4+2] * inv; o.w = v[it*4+3] * inv;
        ((float4*)arow)[j] = o;
    }
}

// ===========================================================================
// Kernel 4: out[b,c,m] = sum_l v[b,c,l] * att[b,m,l], tf32 mma (proven in R4)
// ===========================================================================
__global__ __launch_bounds__(256, 2) void out_gemm_mma_kernel(
    const float* __restrict__ att, float* __restrict__ out)
{
    __shared__ __align__(16) float As[128][36];   // V tile   [c-row][k=l]
    __shared__ __align__(16) float Bs[128][36];   // Att tile [m-row][k=l]

    const int b  = blockIdx.z;
    const int m0 = blockIdx.x * 128;
    const int c0 = blockIdx.y * 128;
    const int tid  = threadIdx.x;
    const int warp = tid >> 5;
    const int lane = tid & 31;
    const int warp_m = (warp & 1) * 64;
    const int warp_n = (warp >> 1) * 32;
    const int r  = lane >> 2;
    const int c4 = lane & 3;

    const float* vb = g_v + (size_t)b * C_ * L_;
    const float* ab = att + (size_t)b * L_ * L_;

    const int rowL = tid >> 3;
    const int q    = tid & 7;

    float acc[4][4][4] = {};

    const int kend = m0 + 128;
    for (int lc = 0; lc < kend; lc += 32) {
        #pragma unroll
        for (int i = 0; i < 4; i++) {
            const int rr = rowL + i * 32;
            float4 a4 = *(const float4*)(vb + (size_t)(c0 + rr) * L_ + lc + q * 4);
            float4 b4 = *(const float4*)(ab + (size_t)(m0 + rr) * L_ + lc + q * 4);
            uint4 au, bu;
            au.x = f2tf32(a4.x); au.y = f2tf32(a4.y); au.z = f2tf32(a4.z); au.w = f2tf32(a4.w);
            bu.x = f2tf32(b4.x); bu.y = f2tf32(b4.y); bu.z = f2tf32(b4.z); bu.w = f2tf32(b4.w);
            *(uint4*)&As[rr][q * 4] = au;
            *(uint4*)&Bs[rr][q * 4] = bu;
        }
        __syncthreads();

        #pragma unroll
        for (int ks = 0; ks < 4; ks++) {
            const int k8 = ks * 8;
            uint32_t af[4][4], bf[4][2];
            #pragma unroll
            for (int mt = 0; mt < 4; mt++) {
                const int ar = warp_m + mt * 16 + r;
                af[mt][0] = __float_as_uint(As[ar    ][k8 + c4]);
                af[mt][1] = __float_as_uint(As[ar + 8][k8 + c4]);
                af[mt][2] = __float_as_uint(As[ar    ][k8 + c4 + 4]);
                af[mt][3] = __float_as_uint(As[ar + 8][k8 + c4 + 4]);
            }
            #pragma unroll
            for (int nt = 0; nt < 4; nt++) {
                const int br = warp_n + nt * 8 + r;
                bf[nt][0] = __float_as_uint(Bs[br][k8 + c4]);
                bf[nt][1] = __float_as_uint(Bs[br][k8 + c4 + 4]);
            }
            #pragma unroll
            for (int mt = 0; mt < 4; mt++)
                #pragma unroll
                for (int nt = 0; nt < 4; nt++)
                    MMA_TF32(acc[mt][nt], af[mt], bf[nt]);
        }
        __syncthreads();
    }

    float* ob = out + (size_t)b * C_ * L_;
    #pragma unroll
    for (int mt = 0; mt < 4; mt++) {
        const int crow = c0 + warp_m + mt * 16 + r;
        #pragma unroll
        for (int nt = 0; nt < 4; nt++) {
            const int mcol = m0 + warp_n + nt * 8 + c4 * 2;
            float2 o0 = make_float2(acc[mt][nt][0], acc[mt][nt][1]);
            float2 o1 = make_float2(acc[mt][nt][2], acc[mt][nt][3]);
            *(float2*)(ob + (size_t)crow       * L_ + mcol) = o0;
            *(float2*)(ob + (size_t)(crow + 8) * L_ + mcol) = o1;
        }
    }
}

// ===========================================================================
extern "C" void kernel_launch(void* const* d_in, const int* in_sizes, int n_in,
                              void* d_out, int out_size)
{
    (void)in_sizes; (void)n_in; (void)out_size;
    const float* x          = (const float*)d_in[0];
    const unsigned char* dm = (const unsigned char*)d_in[1];
    const float* Wq = (const float*)d_in[2];
    const float* bq = (const float*)d_in[3];
    const float* Wk = (const float*)d_in[4];
    const float* bk = (const float*)d_in[5];
    const float* Wv = (const float*)d_in[6];
    const float* bv = (const float*)d_in[7];

    float* out = (float*)d_out;                      // (B, C, L)
    float* att = out + (size_t)B_ * C_ * L_;         // (B, L, L)

    qkv_proj_mma_kernel<<<dim3(L_/128, 640/128, B_), 256>>>(x, Wq, bq, Wk, bk, Wv, bv);
    energy_mma_kernel  <<<dim3(L_/128, L_/128, B_), 256>>>(att);
    softmax_kernel     <<<dim3(L_, B_), 256>>>(att, dm);
    out_gemm_mma_kernel<<<dim3(L_/128, C_/128, B_), 256>>>(att, out);
}

// round 7
// speedup vs baseline: 3.0257x; 1.1312x over previous
#include <cuda_runtime.h>
#include <math.h>
#include <stdint.h>

#define B_ 8
#define C_ 512
#define L_ 2048
#define D_ 64

// Scratch (allocation-free rule: device globals)
__device__ float g_q[B_*D_*L_];          // (b, d, l)
__device__ float g_k[B_*D_*L_];          // (b, d, l)
__device__ float g_v[(size_t)B_*C_*L_];  // (b, c, l)

__device__ __forceinline__ uint32_t f2tf32(float f) {
    uint32_t u;
    asm("cvt.rna.tf32.f32 %0, %1;" : "=r"(u) : "f"(f));
    return u;
}
__device__ __forceinline__ uint32_t smem_u32(const void* p) {
    uint32_t a;
    asm("{ .reg .u64 t; cvta.to.shared.u64 t, %1; cvt.u32.u64 %0, t; }"
        : "=r"(a) : "l"(p));
    return a;
}
__device__ __forceinline__ void cp_async16(uint32_t dst, const void* src) {
    asm volatile("cp.async.ca.shared.global [%0], [%1], 16;"
                 :: "r"(dst), "l"(src));
}
#define CP_COMMIT() asm volatile("cp.async.commit_group;" ::: "memory")
#define CP_WAIT1()  asm volatile("cp.async.wait_group 1;" ::: "memory")
#define CP_WAIT0()  asm volatile("cp.async.wait_group 0;" ::: "memory")

#define MMA_TF32(acc, af, bf)                                                  \
    asm volatile(                                                              \
        "mma.sync.aligned.m16n8k8.row.col.f32.tf32.tf32.f32 "                  \
        "{%0,%1,%2,%3}, {%4,%5,%6,%7}, {%8,%9}, {%0,%1,%2,%3};"                \
        : "+f"((acc)[0]), "+f"((acc)[1]), "+f"((acc)[2]), "+f"((acc)[3])       \
        : "r"((af)[0]), "r"((af)[1]), "r"((af)[2]), "r"((af)[3]),              \
          "r"((bf)[0]), "r"((bf)[1]))

__device__ __forceinline__ const float* w_row_ptr(
    int r, const float* Wq, const float* Wk, const float* Wv)
{
    return (r < 64)  ? Wq + (size_t)r * C_
         : (r < 128) ? Wk + (size_t)(r - 64) * C_
                     : Wv + (size_t)(r - 128) * C_;
}

// ===========================================================================
// Kernel 1: fused QKV projection, tf32 mma + cp.async double buffering.
// As [row][k] stride 36; Bs [k][l] stride 136. 2 stages.
// Stage layout (floats): stage st at st*8960: As 4608, then Bs 4352.
// ===========================================================================
#define QKV_STAGE_F 8960
#define QKV_SMEM_BYTES (2 * QKV_STAGE_F * 4)   // 71680

__global__ __launch_bounds__(256, 2) void qkv_proj_mma_kernel(
    const float* __restrict__ x,
    const float* __restrict__ Wq, const float* __restrict__ bq,
    const float* __restrict__ Wk, const float* __restrict__ bk,
    const float* __restrict__ Wv, const float* __restrict__ bv)
{
    extern __shared__ __align__(16) float sm[];

    const int b  = blockIdx.z;
    const int l0 = blockIdx.x * 128;
    const int r0 = blockIdx.y * 128;
    const int tid  = threadIdx.x;
    const int warp = tid >> 5;
    const int lane = tid & 31;
    const int warp_m = (warp & 1) * 64;
    const int warp_n = (warp >> 1) * 32;
    const int r  = lane >> 2;
    const int c4 = lane & 3;
    const uint32_t sbase = smem_u32(sm);

    const float* xb = x + (size_t)b * C_ * L_;

    const int rowL = tid >> 3;            // 0..31
    const int q8   = tid & 7;

    float acc[4][4][4] = {};

    auto load_slab = [&](int s) {
        const int st = s & 1;
        const int kc = s * 32;
        const uint32_t aoff = sbase + (uint32_t)(st * QKV_STAGE_F) * 4u;
        const uint32_t boff = aoff + 4608u * 4u;
        #pragma unroll
        for (int i = 0; i < 4; i++) {
            const int rr = rowL + i * 32;
            const float* wp = w_row_ptr(r0 + rr, Wq, Wk, Wv);
            cp_async16(aoff + ((uint32_t)rr * 36u + q8 * 4u) * 4u, wp + kc + q8 * 4);
            const int d  = (tid + i * 256) >> 5;
            const int l4 = (tid + i * 256) & 31;
            cp_async16(boff + ((uint32_t)d * 136u + l4 * 4u) * 4u,
                       xb + (size_t)(kc + d) * L_ + l0 + l4 * 4);
        }
        CP_COMMIT();
    };

    const int nst = C_ / 32;   // 16
    load_slab(0);

    for (int s = 0; s < nst; s++) {
        if (s + 1 < nst) { load_slab(s + 1); CP_WAIT1(); }
        else             { CP_WAIT0(); }
        __syncthreads();

        const float* As = sm + (s & 1) * QKV_STAGE_F;
        const float* Bs = As + 4608;

        #pragma unroll
        for (int ks = 0; ks < 4; ks++) {
            const int k8 = ks * 8;
            uint32_t af[4][4], bf[4][2];
            #pragma unroll
            for (int mt = 0; mt < 4; mt++) {
                const int ar = warp_m + mt * 16 + r;
                af[mt][0] = f2tf32(As[(ar    ) * 36 + k8 + c4]);
                af[mt][1] = f2tf32(As[(ar + 8) * 36 + k8 + c4]);
                af[mt][2] = f2tf32(As[(ar    ) * 36 + k8 + c4 + 4]);
                af[mt][3] = f2tf32(As[(ar + 8) * 36 + k8 + c4 + 4]);
            }
            #pragma unroll
            for (int nt = 0; nt < 4; nt++) {
                const int bn = warp_n + nt * 8 + r;
                bf[nt][0] = f2tf32(Bs[(k8 + c4    ) * 136 + bn]);
                bf[nt][1] = f2tf32(Bs[(k8 + c4 + 4) * 136 + bn]);
            }
            #pragma unroll
            for (int mt = 0; mt < 4; mt++)
                #pragma unroll
                for (int nt = 0; nt < 4; nt++)
                    MMA_TF32(acc[mt][nt], af[mt], bf[nt]);
        }
        __syncthreads();
    }

    #pragma unroll
    for (int mt = 0; mt < 4; mt++) {
        #pragma unroll
        for (int half = 0; half < 2; half++) {
            const int rr = r0 + warp_m + mt * 16 + r + half * 8;
            float bias; float* dst;
            if (rr < 64)       { bias = bq[rr];      dst = g_q + ((size_t)b*D_ + rr)       * L_; }
            else if (rr < 128) { bias = bk[rr-64];   dst = g_k + ((size_t)b*D_ + (rr-64))  * L_; }
            else               { bias = bv[rr-128];  dst = g_v + ((size_t)b*C_ + (rr-128)) * L_; }
            #pragma unroll
            for (int nt = 0; nt < 4; nt++) {
                const int col = l0 + warp_n + nt * 8 + c4 * 2;
                float2 o;
                o.x = acc[mt][nt][half*2 + 0] + bias;
                o.y = acc[mt][nt][half*2 + 1] + bias;
                *(float2*)(dst + col) = o;
            }
        }
    }
}

// ===========================================================================
// Kernel 2: energy, 3xTF32 (hi/lo split of q and k, 3 MMAs) -- near-fp32
// accuracy on the tensor pipe. Lower-tri tiles only. BK=32, 2 passes.
// smem (floats): Qhi@0, Qlo@4352, Khi@8704, Klo@13056, each [32][136].
// ===========================================================================
#define EN_SMEM_BYTES (17408 * 4)   // 69632

__global__ __launch_bounds__(256, 2) void energy_mma_kernel(float* __restrict__ att)
{
    extern __shared__ __align__(16) float sm[];
    float* Qhi = sm;
    float* Qlo = sm + 4352;
    float* Khi = sm + 8704;
    float* Klo = sm + 13056;

    const int b  = blockIdx.z;
    const int lt = blockIdx.y;
    const int mt_ = blockIdx.x;
    if (mt_ > lt) return;
    const int l0 = lt * 128, m0 = mt_ * 128;
    const int tid  = threadIdx.x;
    const int warp = tid >> 5;
    const int lane = tid & 31;
    const int warp_m = (warp & 1) * 64;
    const int warp_n = (warp >> 1) * 32;
    const int r  = lane >> 2;
    const int c4 = lane & 3;

    const float* qb = g_q + (size_t)b * D_ * L_;
    const float* kb = g_k + (size_t)b * D_ * L_;

    float acc[4][4][4] = {};

    #pragma unroll
    for (int kc = 0; kc < 64; kc += 32) {
        #pragma unroll
        for (int it = 0; it < 4; it++) {
            const int f  = tid + it * 256;
            const int d  = f >> 5;
            const int l4 = f & 31;
            float4 a4 = *(const float4*)(qb + (size_t)(kc + d) * L_ + l0 + l4 * 4);
            float4 b4 = *(const float4*)(kb + (size_t)(kc + d) * L_ + m0 + l4 * 4);
            float ah[4], al[4], bh[4], bl[4];
            const float av[4] = {a4.x, a4.y, a4.z, a4.w};
            const float bv_[4] = {b4.x, b4.y, b4.z, b4.w};
            #pragma unroll
            for (int c = 0; c < 4; c++) {
                ah[c] = __uint_as_float(f2tf32(av[c]));
                al[c] = __uint_as_float(f2tf32(av[c] - ah[c]));
                bh[c] = __uint_as_float(f2tf32(bv_[c]));
                bl[c] = __uint_as_float(f2tf32(bv_[c] - bh[c]));
            }
            const int o = d * 136 + l4 * 4;
            *(float4*)&Qhi[o] = make_float4(ah[0], ah[1], ah[2], ah[3]);
            *(float4*)&Qlo[o] = make_float4(al[0], al[1], al[2], al[3]);
            *(float4*)&Khi[o] = make_float4(bh[0], bh[1], bh[2], bh[3]);
            *(float4*)&Klo[o] = make_float4(bl[0], bl[1], bl[2], bl[3]);
        }
        __syncthreads();

        #pragma unroll
        for (int ks = 0; ks < 4; ks++) {
            const int k8 = ks * 8;
            uint32_t bfh[4][2], bfl[4][2];
            #pragma unroll
            for (int nt = 0; nt < 4; nt++) {
                const int bn = warp_n + nt * 8 + r;
                bfh[nt][0] = __float_as_uint(Khi[(k8 + c4    ) * 136 + bn]);
                bfh[nt][1] = __float_as_uint(Khi[(k8 + c4 + 4) * 136 + bn]);
                bfl[nt][0] = __float_as_uint(Klo[(k8 + c4    ) * 136 + bn]);
                bfl[nt][1] = __float_as_uint(Klo[(k8 + c4 + 4) * 136 + bn]);
            }
            #pragma unroll
            for (int mt = 0; mt < 4; mt++) {
                const int al_ = warp_m + mt * 16 + r;
                uint32_t afh[4], afl[4];
                afh[0] = __float_as_uint(Qhi[(k8 + c4    ) * 136 + al_]);
                afh[1] = __float_as_uint(Qhi[(k8 + c4    ) * 136 + al_ + 8]);
                afh[2] = __float_as_uint(Qhi[(k8 + c4 + 4) * 136 + al_]);
                afh[3] = __float_as_uint(Qhi[(k8 + c4 + 4) * 136 + al_ + 8]);
                afl[0] = __float_as_uint(Qlo[(k8 + c4    ) * 136 + al_]);
                afl[1] = __float_as_uint(Qlo[(k8 + c4    ) * 136 + al_ + 8]);
                afl[2] = __float_as_uint(Qlo[(k8 + c4 + 4) * 136 + al_]);
                afl[3] = __float_as_uint(Qlo[(k8 + c4 + 4) * 136 + al_ + 8]);
                #pragma unroll
                for (int nt = 0; nt < 4; nt++) {
                    MMA_TF32(acc[mt][nt], afh, bfh[nt]);
                    MMA_TF32(acc[mt][nt], afh, bfl[nt]);
                    MMA_TF32(acc[mt][nt], afl, bfh[nt]);
                }
            }
        }
        __syncthreads();
    }

    float* ab = att + (size_t)b * L_ * L_;
    #pragma unroll
    for (int mt = 0; mt < 4; mt++) {
        #pragma unroll
        for (int half = 0; half < 2; half++) {
            const int l = l0 + warp_m + mt * 16 + r + half * 8;
            #pragma unroll
            for (int nt = 0; nt < 4; nt++) {
                const int m = m0 + warp_n + nt * 8 + c4 * 2;
                float2 o;
                o.x = acc[mt][nt][half*2 + 0];
                o.y = acc[mt][nt][half*2 + 1];
                *(float2*)(ab + (size_t)l * L_ + m) = o;
            }
        }
    }
}

// ===========================================================================
// Kernel 3: register-resident causal softmax (proven)
// ===========================================================================
__device__ __forceinline__ float block_reduce8(float v, float* red, bool is_max)
{
    #pragma unroll
    for (int o = 16; o > 0; o >>= 1) {
        const float t = __shfl_xor_sync(0xffffffffu, v, o);
        v = is_max ? fmaxf(v, t) : (v + t);
    }
    const int w = threadIdx.x >> 5;
    if ((threadIdx.x & 31) == 0) red[w] = v;
    __syncthreads();
    if (threadIdx.x < 32) {
        float t = (threadIdx.x < 8) ? red[threadIdx.x] : (is_max ? -INFINITY : 0.0f);
        #pragma unroll
        for (int o = 4; o > 0; o >>= 1) {
            const float u = __shfl_xor_sync(0xffffffffu, t, o);
            t = is_max ? fmaxf(t, u) : (t + u);
        }
        if (threadIdx.x == 0) red[0] = t;
    }
    __syncthreads();
    const float r = red[0];
    __syncthreads();
    return r;
}

__global__ __launch_bounds__(256) void softmax_kernel(
    float* __restrict__ att, const unsigned char* __restrict__ dmask)
{
    const int l = blockIdx.x;
    const int b = blockIdx.y;
    const int tid = threadIdx.x;

    __shared__ float red[8];

    float* arow = att + ((size_t)b * L_ + l) * L_;
    const uchar4* mrow = (const uchar4*)(dmask + ((size_t)b * L_ + l) * L_);
    const int n = l + 1;

    float v[8];
    float lmax = -INFINITY;
    #pragma unroll
    for (int it = 0; it < 2; it++) {
        const int j = tid + it * 256;
        const int base = j * 4;
        float4 e4 = ((const float4*)arow)[j];
        uchar4 m4 = mrow[j];
        v[it*4+0] = (base+0 < n && !m4.x) ? e4.x : -INFINITY;
        v[it*4+1] = (base+1 < n && !m4.y) ? e4.y : -INFINITY;
        v[it*4+2] = (base+2 < n && !m4.z) ? e4.z : -INFINITY;
        v[it*4+3] = (base+3 < n && !m4.w) ? e4.w : -INFINITY;
        #pragma unroll
        for (int c = 0; c < 4; c++) lmax = fmaxf(lmax, v[it*4+c]);
    }
    const float rmax = block_reduce8(lmax, red, true);

    float lsum = 0.0f;
    #pragma unroll
    for (int c = 0; c < 8; c++) {
        const float p = (v[c] == -INFINITY) ? 0.0f : __expf(v[c] - rmax);
        v[c] = p;
        lsum += p;
    }
    const float rsum = block_reduce8(lsum, red, false);
    const float inv = 1.0f / rsum;

    #pragma unroll
    for (int it = 0; it < 2; it++) {
        const int j = tid + it * 256;
        float4 o;
        o.x = v[it*4+0] * inv; o.y = v[it*4+1] * inv;
        o.z = v[it*4+2] * inv; o.w = v[it*4+3] * inv;
        ((float4*)arow)[j] = o;
    }
}

// ===========================================================================
// Kernel 4: out[b,c,m] = sum_l v[b,c,l]*att[b,m,l], tf32 mma + cp.async
// double buffering. Stage layout (floats): stage st at st*9216:
// As (V) 4608, Bs (att) 4608; both [128][36].
// ===========================================================================
#define OG_STAGE_F 9216
#define OG_SMEM_BYTES (2 * OG_STAGE_F * 4)   // 73728

__global__ __launch_bounds__(256, 2) void out_gemm_mma_kernel(
    const float* __restrict__ att, float* __restrict__ out)
{
    extern __shared__ __align__(16) float sm[];

    const int b  = blockIdx.z;
    const int m0 = blockIdx.x * 128;
    const int c0 = blockIdx.y * 128;
    const int tid  = threadIdx.x;
    const int warp = tid >> 5;
    const int lane = tid & 31;
    const int warp_m = (warp & 1) * 64;
    const int warp_n = (warp >> 1) * 32;
    const int r  = lane >> 2;
    const int c4 = lane & 3;
    const uint32_t sbase = smem_u32(sm);

    const float* vb = g_v + (size_t)b * C_ * L_;
    const float* ab = att + (size_t)b * L_ * L_;

    const int rowL = tid >> 3;
    const int q    = tid & 7;

    float acc[4][4][4] = {};

    auto load_slab = [&](int s) {
        const int st = s & 1;
        const int lc = s * 32;
        const uint32_t aoff = sbase + (uint32_t)(st * OG_STAGE_F) * 4u;
        const uint32_t boff = aoff + 4608u * 4u;
        #pragma unroll
        for (int i = 0; i < 4; i++) {
            const int rr = rowL + i * 32;
            const uint32_t so = ((uint32_t)rr * 36u + q * 4u) * 4u;
            cp_async16(aoff + so, vb + (size_t)(c0 + rr) * L_ + lc + q * 4);
            cp_async16(boff + so, ab + (size_t)(m0 + rr) * L_ + lc + q * 4);
        }
        CP_COMMIT();
    };

    const int nst = (m0 + 128) / 32;   // causal truncation, >= 4
    load_slab(0);

    for (int s = 0; s < nst; s++) {
        if (s + 1 < nst) { load_slab(s + 1); CP_WAIT1(); }
        else             { CP_WAIT0(); }
        __syncthreads();

        const float* As = sm + (s & 1) * OG_STAGE_F;
        const float* Bs = As + 4608;

        #pragma unroll
        for (int ks = 0; ks < 4; ks++) {
            const int k8 = ks * 8;
            uint32_t af[4][4], bf[4][2];
            #pragma unroll
            for (int mt = 0; mt < 4; mt++) {
                const int ar = warp_m + mt * 16 + r;
                af[mt][0] = f2tf32(As[(ar    ) * 36 + k8 + c4]);
                af[mt][1] = f2tf32(As[(ar + 8) * 36 + k8 + c4]);
                af[mt][2] = f2tf32(As[(ar    ) * 36 + k8 + c4 + 4]);
                af[mt][3] = f2tf32(As[(ar + 8) * 36 + k8 + c4 + 4]);
            }
            #pragma unroll
            for (int nt = 0; nt < 4; nt++) {
                const int br = warp_n + nt * 8 + r;
                bf[nt][0] = f2tf32(Bs[(br) * 36 + k8 + c4]);
                bf[nt][1] = f2tf32(Bs[(br) * 36 + k8 + c4 + 4]);
            }
            #pragma unroll
            for (int mt = 0; mt < 4; mt++)
                #pragma unroll
                for (int nt = 0; nt < 4; nt++)
                    MMA_TF32(acc[mt][nt], af[mt], bf[nt]);
        }
        __syncthreads();
    }

    float* ob = out + (size_t)b * C_ * L_;
    #pragma unroll
    for (int mt = 0; mt < 4; mt++) {
        const int crow = c0 + warp_m + mt * 16 + r;
        #pragma unroll
        for (int nt = 0; nt < 4; nt++) {
            const int mcol = m0 + warp_n + nt * 8 + c4 * 2;
            float2 o0 = make_float2(acc[mt][nt][0], acc[mt][nt][1]);
            float2 o1 = make_float2(acc[mt][nt][2], acc[mt][nt][3]);
            *(float2*)(ob + (size_t)crow       * L_ + mcol) = o0;
            *(float2*)(ob + (size_t)(crow + 8) * L_ + mcol) = o1;
        }
    }
}

// ===========================================================================
extern "C" void kernel_launch(void* const* d_in, const int* in_sizes, int n_in,
                              void* d_out, int out_size)
{
    (void)in_sizes; (void)n_in; (void)out_size;
    const float* x          = (const float*)d_in[0];
    const unsigned char* dm = (const unsigned char*)d_in[1];
    const float* Wq = (const float*)d_in[2];
    const float* bq = (const float*)d_in[3];
    const float* Wk = (const float*)d_in[4];
    const float* bk = (const float*)d_in[5];
    const float* Wv = (const float*)d_in[6];
    const float* bv = (const float*)d_in[7];

    float* out = (float*)d_out;                      // (B, C, L)
    float* att = out + (size_t)B_ * C_ * L_;         // (B, L, L)

    cudaFuncSetAttribute(qkv_proj_mma_kernel,
                         cudaFuncAttributeMaxDynamicSharedMemorySize, QKV_SMEM_BYTES);
    cudaFuncSetAttribute(energy_mma_kernel,
                         cudaFuncAttributeMaxDynamicSharedMemorySize, EN_SMEM_BYTES);
    cudaFuncSetAttribute(out_gemm_mma_kernel,
                         cudaFuncAttributeMaxDynamicSharedMemorySize, OG_SMEM_BYTES);

    qkv_proj_mma_kernel<<<dim3(L_/128, 640/128, B_), 256, QKV_SMEM_BYTES>>>(
        x, Wq, bq, Wk, bk, Wv, bv);
    energy_mma_kernel  <<<dim3(L_/128, L_/128, B_), 256, EN_SMEM_BYTES>>>(att);
    softmax_kernel     <<<dim3(L_, B_), 256>>>(att, dm);
    out_gemm_mma_kernel<<<dim3(L_/128, C_/128, B_), 256, OG_SMEM_BYTES>>>(att, out);
}